// round 9
// baseline (speedup 1.0000x reference)
#include <cuda_runtime.h>
#include <cuda_bf16.h>
#include <math.h>
#include <stdint.h>

// ---------------- scratch (static device arrays; no allocation) ----------------
__device__ float g_qkv[16384 * 1536];      // QKV projection output
__device__ float g_scores[64 * 512 * 512]; // attention scores / probs
__device__ float g_attn[16384 * 512];      // attention output (pre out-proj)
__device__ float g_dec[16384 * 512];       // decoder features after ReLU
__device__ float g_em[16384 * 24];         // CRF emissions
__device__ float g_llh[32];                // per-batch (num - den)

// ---------------- tf32 split helper (hi/lo, ~2^-22 combined precision) --------
__device__ __forceinline__ void split_tf32(float x, uint32_t& h, uint32_t& l)
{
    uint32_t hu;
    asm("cvt.rna.tf32.f32 %0, %1;" : "=r"(hu) : "f"(x));
    float lf = x - __uint_as_float(hu);
    uint32_t lu;
    asm("cvt.rna.tf32.f32 %0, %1;" : "=r"(lu) : "f"(lf));
    h = hu; l = lu;
}

#define MMA_TF32(d, a, b0, b1)                                              \
    asm("mma.sync.aligned.m16n8k8.row.col.f32.tf32.tf32.f32 "               \
        "{%0,%1,%2,%3}, {%4,%5,%6,%7}, {%8,%9}, {%0,%1,%2,%3};"             \
        : "+f"(d[0]), "+f"(d[1]), "+f"(d[2]), "+f"(d[3])                    \
        : "r"(a[0]), "r"(a[1]), "r"(a[2]), "r"(a[3]), "r"(b0), "r"(b1))

// ---------------- fragment-major smem offsets ---------------------------------
// A element (row m 0..127, k 0..15) -> word offset in 2048-word plane.
// Frag for thread(r,cq), tile it, kstep ks: LDS.128 at (((ks*8+it)*8+r)*4+cq)*4
__device__ __forceinline__ int a_off(int m, int k)
{
    int ks = k >> 3, it = m >> 4, r = m & 7, half = (m >> 3) & 1;
    int cq = k & 3, khi = (k >> 2) & 1;
    return ((((ks << 3) + it) * 8 + r) * 4 + cq) * 4 + half + (khi << 1);
}
// B element (n 0..127, k 0..15): pairs (k=cq, k=cq+4) -> LDS.64
__device__ __forceinline__ int b_off(int n, int k)
{
    int ks = k >> 3, cq = k & 3, khi = (k >> 2) & 1;
    return (((ks << 7) + n) * 4 + cq) * 2 + khi;
}

// ---------------- tf32x3 GEMM: C = act(alpha * A @ op(B) + bias) ---------------
// Tile 128x128x16, 8 warps as 2x4 (warp tile 64x32). 2-stage smem ring,
// ONE barrier per chunk: store(c)->buf[c&1]; prefetch LDG(c+1); bar; MMA(c).
#define GBM 128
#define GBN 128
#define GBK 16
#define STAGE_WORDS 8192           // Ah|Al|Bh|Bl, 2048 words each
#define SMEM_BYTES (2 * STAGE_WORDS * 4)

__global__ __launch_bounds__(256, 1) void mma_gemm_kernel(
    const float* __restrict__ A, int lda, long long aOuter, long long aInner,
    const float* __restrict__ B, int ldb, long long bOuter, long long bInner,
    float* __restrict__ C, int ldc, long long cOuter, long long cInner,
    const float* __restrict__ bias,
    int K, float alpha, int flags, int zdiv)
{
    extern __shared__ uint32_t sm[];
    int z = blockIdx.z;
    A += (long long)(z / zdiv) * aOuter + (long long)(z % zdiv) * aInner;
    B += (long long)(z / zdiv) * bOuter + (long long)(z % zdiv) * bInner;
    C += (long long)(z / zdiv) * cOuter + (long long)(z % zdiv) * cInner;

    int tid = threadIdx.x;
    int lane = tid & 31;
    int wid = tid >> 5;
    int r = lane >> 2;         // 0..7
    int cq = lane & 3;         // 0..3
    int wm = (wid >> 2) * 64;  // warp m offset
    int wn = (wid & 3) * 32;   // warp n offset
    int it0 = (wid >> 2) * 4;  // first A i-tile for this warp
    int bm = blockIdx.y * GBM, bn = blockIdx.x * GBN;
    bool transB = (flags & 1) != 0;

    // per-thread load coordinates
    int aRow0 = tid >> 2;            // + aRow1 = aRow0 + 64
    int aCol0 = (tid & 3) * 4;
    int bKk0 = tid >> 5;             // bKk1 = bKk0 + 8
    int bN40 = (tid & 31) * 4;

    float acc[4][4][4];
#pragma unroll
    for (int i = 0; i < 4; i++)
#pragma unroll
        for (int j = 0; j < 4; j++)
#pragma unroll
            for (int q = 0; q < 4; q++) acc[i][j][q] = 0.f;

    float4 pa0, pa1, pb0, pb1;

#define LOAD_CHUNK(c) do {                                                          \
    pa0 = *(const float4*)&A[(long long)(bm + aRow0) * lda + (c) * GBK + aCol0];    \
    pa1 = *(const float4*)&A[(long long)(bm + aRow0 + 64) * lda + (c) * GBK + aCol0];\
    if (transB) {                                                                   \
        pb0 = *(const float4*)&B[(long long)(bn + aRow0) * ldb + (c) * GBK + aCol0];\
        pb1 = *(const float4*)&B[(long long)(bn + aRow0 + 64) * ldb + (c) * GBK + aCol0];\
    } else {                                                                        \
        pb0 = *(const float4*)&B[(long long)((c) * GBK + bKk0) * ldb + bn + bN40];  \
        pb1 = *(const float4*)&B[(long long)((c) * GBK + bKk0 + 8) * ldb + bn + bN40];\
    }                                                                               \
} while (0)

#define STORE_CHUNK(base) do {                                                      \
    uint32_t* sAh = (base);                                                         \
    uint32_t* sAl = (base) + 2048;                                                  \
    uint32_t* sBh = (base) + 4096;                                                  \
    uint32_t* sBl = (base) + 6144;                                                  \
    float av0[4] = {pa0.x, pa0.y, pa0.z, pa0.w};                                    \
    float av1[4] = {pa1.x, pa1.y, pa1.z, pa1.w};                                    \
    float bv0[4] = {pb0.x, pb0.y, pb0.z, pb0.w};                                    \
    float bv1[4] = {pb1.x, pb1.y, pb1.z, pb1.w};                                    \
    _Pragma("unroll")                                                               \
    for (int q = 0; q < 4; q++) {                                                   \
        uint32_t h, l;                                                              \
        split_tf32(av0[q], h, l);                                                   \
        int o = a_off(aRow0, aCol0 + q);                                            \
        sAh[o] = h; sAl[o] = l;                                                     \
        split_tf32(av1[q], h, l);                                                   \
        o = a_off(aRow0 + 64, aCol0 + q);                                           \
        sAh[o] = h; sAl[o] = l;                                                     \
        if (transB) {                                                               \
            split_tf32(bv0[q], h, l);                                               \
            o = b_off(aRow0, aCol0 + q);                                            \
            sBh[o] = h; sBl[o] = l;                                                 \
            split_tf32(bv1[q], h, l);                                               \
            o = b_off(aRow0 + 64, aCol0 + q);                                       \
            sBh[o] = h; sBl[o] = l;                                                 \
        } else {                                                                    \
            split_tf32(bv0[q], h, l);                                               \
            o = b_off(bN40 + q, bKk0);                                              \
            sBh[o] = h; sBl[o] = l;                                                 \
            split_tf32(bv1[q], h, l);                                               \
            o = b_off(bN40 + q, bKk0 + 8);                                          \
            sBh[o] = h; sBl[o] = l;                                                 \
        }                                                                           \
    }                                                                               \
} while (0)

    int nk = K / GBK;
    LOAD_CHUNK(0);

    for (int c = 0; c < nk; c++) {
        uint32_t* base = sm + (c & 1) * STAGE_WORDS;
        STORE_CHUNK(base);                 // regs hold chunk c
        if (c + 1 < nk) LOAD_CHUNK(c + 1); // prefetch overlaps MMA below
        __syncthreads();                   // buf[c&1] ready; also frees via MMA(c-2) done

        uint32_t* sAh = base;
        uint32_t* sAl = base + 2048;
        uint32_t* sBh = base + 4096;
        uint32_t* sBl = base + 6144;

#pragma unroll
        for (int ks = 0; ks < 2; ks++) {
            uint32_t afh[4][4], afl[4][4];
#pragma unroll
            for (int i = 0; i < 4; i++) {
                int wo = ks * 1024 + (((it0 + i) * 8 + r) * 4 + cq) * 4;
                uint4 hv = *(const uint4*)&sAh[wo];
                uint4 lv = *(const uint4*)&sAl[wo];
                afh[i][0] = hv.x; afh[i][1] = hv.y; afh[i][2] = hv.z; afh[i][3] = hv.w;
                afl[i][0] = lv.x; afl[i][1] = lv.y; afl[i][2] = lv.z; afl[i][3] = lv.w;
            }
#pragma unroll
            for (int j = 0; j < 4; j++) {
                int wo = ((ks * 128 + wn + 8 * j + r) * 4 + cq) * 2;
                uint2 bh = *(const uint2*)&sBh[wo];
                uint2 bl = *(const uint2*)&sBl[wo];
#pragma unroll
                for (int i = 0; i < 4; i++) {
                    MMA_TF32(acc[i][j], afh[i], bh.x, bh.y);  // hi * hi
                    MMA_TF32(acc[i][j], afl[i], bh.x, bh.y);  // lo * hi
                    MMA_TF32(acc[i][j], afh[i], bl.x, bl.y);  // hi * lo
                }
            }
        }
    }

    // ---- epilogue ----
    bool relu = (flags & 2) != 0;
#pragma unroll
    for (int i = 0; i < 4; i++) {
        int row0 = bm + wm + 16 * i + r;
#pragma unroll
        for (int j = 0; j < 4; j++) {
            int col0 = bn + wn + 8 * j + 2 * cq;
            float bv0 = bias ? bias[col0] : 0.f;
            float bv1 = bias ? bias[col0 + 1] : 0.f;
            float v0 = alpha * acc[i][j][0] + bv0;
            float v1 = alpha * acc[i][j][1] + bv1;
            float v2 = alpha * acc[i][j][2] + bv0;
            float v3 = alpha * acc[i][j][3] + bv1;
            if (relu) {
                v0 = fmaxf(v0, 0.f); v1 = fmaxf(v1, 0.f);
                v2 = fmaxf(v2, 0.f); v3 = fmaxf(v3, 0.f);
            }
            *(float2*)&C[(long long)row0 * ldc + col0] = make_float2(v0, v1);
            *(float2*)&C[(long long)(row0 + 8) * ldc + col0] = make_float2(v2, v3);
        }
    }
#undef LOAD_CHUNK
#undef STORE_CHUNK
}

// ---------------- row softmax over 512 columns (warp per row) ----------------
__global__ __launch_bounds__(256) void softmax_rows(float* __restrict__ s)
{
    int row = blockIdx.x * 8 + (threadIdx.x >> 5);
    int lane = threadIdx.x & 31;
    float* p = s + (long long)row * 512;

    float v[16];
    float m = -1e30f;
#pragma unroll
    for (int i = 0; i < 16; i++) {
        v[i] = p[lane + 32 * i];
        m = fmaxf(m, v[i]);
    }
#pragma unroll
    for (int off = 16; off; off >>= 1) m = fmaxf(m, __shfl_xor_sync(0xffffffffu, m, off));
    float sum = 0.f;
#pragma unroll
    for (int i = 0; i < 16; i++) {
        v[i] = expf(v[i] - m);   // accurate exp: Viterbi-upstream
        sum += v[i];
    }
#pragma unroll
    for (int off = 16; off; off >>= 1) sum += __shfl_xor_sync(0xffffffffu, sum, off);
    float inv = 1.f / sum;
#pragma unroll
    for (int i = 0; i < 16; i++) p[lane + 32 * i] = v[i] * inv;
}

// ---------------- emissions (24 CRF logits) + 2-class log-softmax head --------
__global__ __launch_bounds__(256) void emissions_kernel(
    const float* __restrict__ dec,
    const float* __restrict__ crf_w, const float* __restrict__ crf_b,
    const float* __restrict__ ent_w, const float* __restrict__ ent_b,
    float* __restrict__ em, float* __restrict__ seg_out)
{
    int row = blockIdx.x * 8 + (threadIdx.x >> 5);
    int lane = threadIdx.x & 31;
    const float* a = dec + (long long)row * 512;

    float acc[26];
#pragma unroll
    for (int o = 0; o < 26; o++) acc[o] = 0.f;

    for (int kk = lane; kk < 512; kk += 32) {
        float av = a[kk];
#pragma unroll
        for (int o = 0; o < 24; o++) acc[o] += av * crf_w[o * 512 + kk];
        acc[24] += av * ent_w[kk];
        acc[25] += av * ent_w[512 + kk];
    }
#pragma unroll
    for (int o = 0; o < 26; o++) {
#pragma unroll
        for (int off = 16; off; off >>= 1) acc[o] += __shfl_down_sync(0xffffffffu, acc[o], off);
    }
    if (lane == 0) {
#pragma unroll
        for (int o = 0; o < 24; o++) em[(long long)row * 24 + o] = acc[o] + crf_b[o];
        float z0 = acc[24] + ent_b[0];
        float z1 = acc[25] + ent_b[1];
        float m = fmaxf(z0, z1);
        float l = m + logf(expf(z0 - m) + expf(z1 - m));
        seg_out[(long long)row * 2 + 0] = z0 - l;
        seg_out[(long long)row * 2 + 1] = z1 - l;
    }
}

// ---------------- CRF: numerator + forward (logsumexp) + Viterbi --------------
__global__ __launch_bounds__(64) void crf_kernel(
    const float* __restrict__ em, const int* __restrict__ labels,
    const float* __restrict__ start_t, const float* __restrict__ end_t,
    const float* __restrict__ trans,
    float* __restrict__ out_crf, float* __restrict__ llh_part)
{
    __shared__ float tr[24 * 24];
    __shared__ float lse[24], vit[24];
    __shared__ unsigned char hist[511 * 24];
    __shared__ float red[64];
    __shared__ float s_num;

    int b = blockIdx.x, tid = threadIdx.x;
    const float* e0 = em + (long long)b * 512 * 24;
    const int* lab = labels + b * 512;

    for (int i = tid; i < 576; i += 64) tr[i] = trans[i];
    __syncthreads();

    float local = 0.f;
    for (int t = 1 + tid; t < 512; t += 64) {
        int lp = lab[t - 1], lc = lab[t];
        local += tr[lp * 24 + lc] + e0[t * 24 + lc];
    }
    red[tid] = local;
    if (tid < 24) { float v = start_t[tid] + e0[tid]; lse[tid] = v; vit[tid] = v; }
    __syncthreads();
    if (tid == 0) {
        float s = 0.f;
        for (int i = 0; i < 64; i++) s += red[i];
        int l0 = lab[0], lN = lab[511];
        s_num = s + start_t[l0] + e0[l0] + end_t[lN];
    }
    __syncthreads();

    for (int t = 1; t < 512; t++) {
        const float* e = e0 + t * 24;
        float nl = 0.f, nv = 0.f;
        int bi = 0;
        if (tid < 24) {
            int j = tid;
            float m = -1e30f;
#pragma unroll
            for (int i = 0; i < 24; i++) m = fmaxf(m, lse[i] + tr[i * 24 + j]);
            float s = 0.f;
#pragma unroll
            for (int i = 0; i < 24; i++) s += __expf(lse[i] + tr[i * 24 + j] - m);
            nl = m + __logf(s) + e[j];
        } else if (tid >= 32 && tid < 56) {
            int j = tid - 32;
            float bm = -1e30f;
#pragma unroll
            for (int i = 0; i < 24; i++) {
                float v = vit[i] + tr[i * 24 + j];
                if (v > bm) { bm = v; bi = i; }   // strict > : first-max like jnp.argmax
            }
            nv = bm + e[j];
        }
        __syncthreads();
        if (tid < 24) lse[tid] = nl;
        else if (tid >= 32 && tid < 56) {
            vit[tid - 32] = nv;
            hist[(t - 1) * 24 + (tid - 32)] = (unsigned char)bi;
        }
        __syncthreads();
    }

    if (tid == 0) {
        float m = -1e30f;
        for (int j = 0; j < 24; j++) m = fmaxf(m, lse[j] + end_t[j]);
        float s = 0.f;
        for (int j = 0; j < 24; j++) s += __expf(lse[j] + end_t[j] - m);
        float den = m + __logf(s);
        llh_part[b] = s_num - den;
    }
    if (tid == 32) {
        float bm = -1e30f;
        int last = 0;
        for (int j = 0; j < 24; j++) {
            float v = vit[j] + end_t[j];
            if (v > bm) { bm = v; last = j; }
        }
        out_crf[b * 512 + 511] = (float)last;
        int tag = last;
        for (int t = 510; t >= 0; t--) {
            tag = hist[t * 24 + tag];
            out_crf[b * 512 + t] = (float)tag;
        }
    }
}

__global__ void finalize_kernel(const float* __restrict__ llh_part, float* __restrict__ out_scalar)
{
    if (threadIdx.x == 0) {
        float s = 0.f;
        for (int i = 0; i < 32; i++) s += llh_part[i];
        *out_scalar = -s / 16384.0f;
    }
}

// --------------------------------- launch -------------------------------------
extern "C" void kernel_launch(void* const* d_in, const int* in_sizes, int n_in,
                              void* d_out, int out_size)
{
    const float* enc     = (const float*)d_in[0];   // (32,512,512)
    const int*   labels  = (const int*)d_in[1];     // (32,512)
    // d_in[2] = mask (all ones) — unused
    const float* Win     = (const float*)d_in[3];   // (1536,512)
    const float* bin_    = (const float*)d_in[4];   // (1536,)
    const float* Wout    = (const float*)d_in[5];   // (512,512)
    const float* bout    = (const float*)d_in[6];   // (512,)
    const float* crf_w   = (const float*)d_in[7];   // (24,512)
    const float* crf_b   = (const float*)d_in[8];   // (24,)
    const float* start_t = (const float*)d_in[9];   // (24,)
    const float* end_t   = (const float*)d_in[10];  // (24,)
    const float* trans   = (const float*)d_in[11];  // (24,24)
    const float* ent_w   = (const float*)d_in[12];  // (2,512)
    const float* ent_b   = (const float*)d_in[13];  // (2,)

    float* out = (float*)d_out;  // [crf_out 16384 | seg_out 32768 | -llh 1]

    float *qkv, *scores, *attn, *dec, *em, *llh;
    cudaGetSymbolAddress((void**)&qkv, g_qkv);
    cudaGetSymbolAddress((void**)&scores, g_scores);
    cudaGetSymbolAddress((void**)&attn, g_attn);
    cudaGetSymbolAddress((void**)&dec, g_dec);
    cudaGetSymbolAddress((void**)&em, g_em);
    cudaGetSymbolAddress((void**)&llh, g_llh);

    cudaFuncSetAttribute(mma_gemm_kernel,
                         cudaFuncAttributeMaxDynamicSharedMemorySize, SMEM_BYTES);

    // 1) QKV = enc @ Win^T + bin : (16384 x 1536), K=512
    mma_gemm_kernel<<<dim3(12, 128, 1), 256, SMEM_BYTES>>>(
        enc, 512, 0, 0,
        Win, 512, 0, 0,
        qkv, 1536, 0, 0,
        bin_, 512, 1.0f, /*transB*/1, 1);

    // 2) scores[b,h] = Q @ K^T / 16 : 64 batched (512 x 512), K=256
    mma_gemm_kernel<<<dim3(4, 4, 64), 256, SMEM_BYTES>>>(
        qkv,        1536, 512LL * 1536, 256,
        qkv + 512,  1536, 512LL * 1536, 256,
        scores,     512,  524288LL,     262144LL,
        nullptr, 256, 0.0625f, /*transB*/1, 2);

    // 3) softmax over rows
    softmax_rows<<<4096, 256>>>(scores);

    // 4) attn_out[b,h] = P @ V : 64 batched (512 x 256), K=512
    mma_gemm_kernel<<<dim3(2, 4, 64), 256, SMEM_BYTES>>>(
        scores,      512,  524288LL,     262144LL,
        qkv + 1024,  1536, 512LL * 1536, 256,
        attn,        512,  262144LL,     256LL,
        nullptr, 512, 1.0f, /*transB=0*/0, 2);

    // 5) dec = relu(attn @ Wout^T + bout) : (16384 x 512), K=512
    mma_gemm_kernel<<<dim3(4, 128, 1), 256, SMEM_BYTES>>>(
        attn, 512, 0, 0,
        Wout, 512, 0, 0,
        dec,  512, 0, 0,
        bout, 512, 1.0f, /*transB|relu*/3, 1);

    // 6) emissions (24) + seg log-softmax (2); seg written straight into d_out
    emissions_kernel<<<2048, 256>>>(dec, crf_w, crf_b, ent_w, ent_b, em, out + 16384);

    // 7) CRF scan: numerator + normalizer + Viterbi (+ backtrack into d_out)
    crf_kernel<<<32, 64>>>(em, labels, start_t, end_t, trans, out, llh);

    // 8) scalar -llh
    finalize_kernel<<<1, 32>>>(llh, out + 16384 + 32768);
}

// round 12
// speedup vs baseline: 1.6735x; 1.6735x over previous
#include <cuda_runtime.h>
#include <cuda_fp16.h>
#include <math.h>
#include <stdint.h>

// ---------------- scratch (static device arrays; no allocation) ----------------
__device__ float g_qkv[16384 * 1536];      // QKV projection output
__device__ float g_vt[64 * 256 * 512];     // V transposed per (b,h): [d][s]
__device__ float g_scores[64 * 512 * 512]; // attention scores / probs
__device__ float g_attn[16384 * 512];      // attention output (pre out-proj)
__device__ float g_dec[16384 * 512];       // decoder features after ReLU
__device__ float g_em[16384 * 24];         // CRF emissions
__device__ float g_llh[32];                // per-batch (num - den)

// ---------------- fp16 split helper (hi/lo, ~2^-22 combined precision) --------
__device__ __forceinline__ void pack2(float x0, float x1, uint32_t& h, uint32_t& l)
{
    __half h0 = __float2half_rn(x0);
    __half h1 = __float2half_rn(x1);
    __half l0 = __float2half_rn(x0 - __half2float(h0));
    __half l1 = __float2half_rn(x1 - __half2float(h1));
    h = (uint32_t)__half_as_ushort(h0) | ((uint32_t)__half_as_ushort(h1) << 16);
    l = (uint32_t)__half_as_ushort(l0) | ((uint32_t)__half_as_ushort(l1) << 16);
}

#define MMA_F16(d, a, b0, b1)                                               \
    asm("mma.sync.aligned.m16n8k16.row.col.f32.f16.f16.f32 "                \
        "{%0,%1,%2,%3}, {%4,%5,%6,%7}, {%8,%9}, {%0,%1,%2,%3};"             \
        : "+f"(d[0]), "+f"(d[1]), "+f"(d[2]), "+f"(d[3])                    \
        : "r"(a[0]), "r"(a[1]), "r"(a[2]), "r"(a[3]), "r"(b0), "r"(b1))

// ---------------- fp16x3 GEMM: C = act(alpha * A @ B^T + bias) -----------------
// A: MxK row-major (lda). B: NxK row-major (ldb) -- ALWAYS transB.
// Batched via z: ptr += (z/zdiv)*outer + (z%zdiv)*inner.
// Tile 128x128x16; 8 warps as 2x4 (warp tile 64x32, 4x4 m16n8k16 frags).
// SMEM plane layout: word(cq, idx, khi) = cq*264 + idx*2 + khi
//   (264 == 8 mod 32: frag LDS.64 conflict-free; stores conflict-free.)
#define GBM 128
#define GBN 128
#define GBK 16
#define PLANE 1056
#define STAGE_WORDS (4 * PLANE)    // Ah | Al | Bh | Bl

__global__ __launch_bounds__(256, 1) void mma_gemm_kernel(
    const float* __restrict__ A, int lda, long long aOuter, long long aInner,
    const float* __restrict__ B, int ldb, long long bOuter, long long bInner,
    float* __restrict__ C, int ldc, long long cOuter, long long cInner,
    const float* __restrict__ bias,
    int K, float alpha, int flags, int zdiv)
{
    __shared__ uint32_t sm[2 * STAGE_WORDS];
    int z = blockIdx.z;
    A += (long long)(z / zdiv) * aOuter + (long long)(z % zdiv) * aInner;
    B += (long long)(z / zdiv) * bOuter + (long long)(z % zdiv) * bInner;
    C += (long long)(z / zdiv) * cOuter + (long long)(z % zdiv) * cInner;

    int tid = threadIdx.x;
    int lane = tid & 31;
    int wid = tid >> 5;
    int r = lane >> 2;         // 0..7
    int cq = lane & 3;         // 0..3
    int wm = (wid >> 2) * 64;  // warp m offset
    int wn = (wid & 3) * 32;   // warp n offset
    int bm = blockIdx.y * GBM, bn = blockIdx.x * GBN;

    int aRow0 = tid >> 2;            // 0..63 ; second row = +64
    int kq = tid & 3;                // k-quad: k = 4*kq .. 4*kq+3

    float acc[4][4][4];
#pragma unroll
    for (int i = 0; i < 4; i++)
#pragma unroll
        for (int j = 0; j < 4; j++)
#pragma unroll
            for (int q = 0; q < 4; q++) acc[i][j][q] = 0.f;

    float4 pa0, pa1, pb0, pb1;

#define LOAD_CHUNK(c) do {                                                           \
    pa0 = *(const float4*)&A[(long long)(bm + aRow0) * lda + (c) * GBK + kq * 4];    \
    pa1 = *(const float4*)&A[(long long)(bm + aRow0 + 64) * lda + (c) * GBK + kq * 4];\
    pb0 = *(const float4*)&B[(long long)(bn + aRow0) * ldb + (c) * GBK + kq * 4];    \
    pb1 = *(const float4*)&B[(long long)(bn + aRow0 + 64) * ldb + (c) * GBK + kq * 4];\
} while (0)

    // store one float4 (k = 4kq..4kq+3) of row idx into plane pair
#define STORE_V4(ph, pl, idx, v) do {                                                \
    uint32_t _h, _l;                                                                 \
    int _k2 = 2 * kq;                                                                \
    pack2((v).x, (v).y, _h, _l);                                                     \
    int _o = (_k2 & 3) * 264 + (idx) * 2 + (_k2 >> 2);                               \
    (ph)[_o] = _h; (pl)[_o] = _l;                                                    \
    _k2 = 2 * kq + 1;                                                                \
    pack2((v).z, (v).w, _h, _l);                                                     \
    _o = (_k2 & 3) * 264 + (idx) * 2 + (_k2 >> 2);                                   \
    (ph)[_o] = _h; (pl)[_o] = _l;                                                    \
} while (0)

#define STORE_CHUNK(base) do {                                                       \
    uint32_t* sAh = (base);                                                          \
    uint32_t* sAl = (base) + PLANE;                                                  \
    uint32_t* sBh = (base) + 2 * PLANE;                                              \
    uint32_t* sBl = (base) + 3 * PLANE;                                              \
    STORE_V4(sAh, sAl, aRow0, pa0);                                                  \
    STORE_V4(sAh, sAl, aRow0 + 64, pa1);                                             \
    STORE_V4(sBh, sBl, aRow0, pb0);                                                  \
    STORE_V4(sBh, sBl, aRow0 + 64, pb1);                                             \
} while (0)

    int nk = K / GBK;
    LOAD_CHUNK(0);
    STORE_CHUNK(sm);
    __syncthreads();

    for (int c = 0; c < nk; c++) {
        if (c + 1 < nk) LOAD_CHUNK(c + 1);   // prefetch overlaps MMA below

        uint32_t* base = sm + (c & 1) * STAGE_WORDS;
        uint32_t* sAh = base;
        uint32_t* sAl = base + PLANE;
        uint32_t* sBh = base + 2 * PLANE;
        uint32_t* sBl = base + 3 * PLANE;

        uint32_t afh[4][4], afl[4][4];
#pragma unroll
        for (int i = 0; i < 4; i++) {
            int mi = wm + 16 * i + r;
            uint2 h0 = *(const uint2*)&sAh[cq * 264 + mi * 2];
            uint2 h1 = *(const uint2*)&sAh[cq * 264 + (mi + 8) * 2];
            uint2 l0 = *(const uint2*)&sAl[cq * 264 + mi * 2];
            uint2 l1 = *(const uint2*)&sAl[cq * 264 + (mi + 8) * 2];
            afh[i][0] = h0.x; afh[i][1] = h1.x; afh[i][2] = h0.y; afh[i][3] = h1.y;
            afl[i][0] = l0.x; afl[i][1] = l1.x; afl[i][2] = l0.y; afl[i][3] = l1.y;
        }
#pragma unroll
        for (int j = 0; j < 4; j++) {
            int ni = wn + 8 * j + r;
            uint2 bh = *(const uint2*)&sBh[cq * 264 + ni * 2];
            uint2 bl = *(const uint2*)&sBl[cq * 264 + ni * 2];
#pragma unroll
            for (int i = 0; i < 4; i++) {
                MMA_F16(acc[i][j], afh[i], bh.x, bh.y);  // hi * hi
                MMA_F16(acc[i][j], afl[i], bh.x, bh.y);  // lo * hi
                MMA_F16(acc[i][j], afh[i], bl.x, bl.y);  // hi * lo
            }
        }
        __syncthreads();
        if (c + 1 < nk) {
            STORE_CHUNK(sm + ((c + 1) & 1) * STAGE_WORDS);
            __syncthreads();
        }
    }

    // ---- epilogue ----
    bool relu = (flags & 2) != 0;
#pragma unroll
    for (int i = 0; i < 4; i++) {
        int row0 = bm + wm + 16 * i + r;
#pragma unroll
        for (int j = 0; j < 4; j++) {
            int col0 = bn + wn + 8 * j + 2 * cq;
            float bv0 = bias ? bias[col0] : 0.f;
            float bv1 = bias ? bias[col0 + 1] : 0.f;
            float v0 = alpha * acc[i][j][0] + bv0;
            float v1 = alpha * acc[i][j][1] + bv1;
            float v2 = alpha * acc[i][j][2] + bv0;
            float v3 = alpha * acc[i][j][3] + bv1;
            if (relu) {
                v0 = fmaxf(v0, 0.f); v1 = fmaxf(v1, 0.f);
                v2 = fmaxf(v2, 0.f); v3 = fmaxf(v3, 0.f);
            }
            *(float2*)&C[(long long)row0 * ldc + col0] = make_float2(v0, v1);
            *(float2*)&C[(long long)(row0 + 8) * ldc + col0] = make_float2(v2, v3);
        }
    }
#undef LOAD_CHUNK
#undef STORE_V4
#undef STORE_CHUNK
}

// ---------------- V transpose: qkv V-part (s,d) -> vt[(b,h)][d][s] -------------
__global__ __launch_bounds__(256) void transpose_v(
    const float* __restrict__ qkv, float* __restrict__ vt)
{
    __shared__ float t[32][33];
    int z = blockIdx.z;
    int b = z >> 1, h = z & 1;
    int s0 = blockIdx.x * 32, d0 = blockIdx.y * 32;
    const float* src = qkv + (long long)b * 512 * 1536 + 1024 + h * 256;
#pragma unroll
    for (int yy = 0; yy < 4; yy++) {
        int sl = threadIdx.y + 8 * yy;
        t[sl][threadIdx.x] = src[(long long)(s0 + sl) * 1536 + d0 + threadIdx.x];
    }
    __syncthreads();
    float* dst = vt + (long long)z * 131072 + (long long)d0 * 512 + s0;
#pragma unroll
    for (int yy = 0; yy < 4; yy++) {
        int dl = threadIdx.y + 8 * yy;
        dst[(long long)dl * 512 + threadIdx.x] = t[threadIdx.x][dl];
    }
}

// ---------------- row softmax over 512 columns (warp per row) ----------------
__global__ __launch_bounds__(256) void softmax_rows(float* __restrict__ s)
{
    int row = blockIdx.x * 8 + (threadIdx.x >> 5);
    int lane = threadIdx.x & 31;
    float* p = s + (long long)row * 512;

    float v[16];
    float m = -1e30f;
#pragma unroll
    for (int i = 0; i < 16; i++) {
        v[i] = p[lane + 32 * i];
        m = fmaxf(m, v[i]);
    }
#pragma unroll
    for (int off = 16; off; off >>= 1) m = fmaxf(m, __shfl_xor_sync(0xffffffffu, m, off));
    float sum = 0.f;
#pragma unroll
    for (int i = 0; i < 16; i++) {
        v[i] = expf(v[i] - m);   // accurate exp: Viterbi-upstream
        sum += v[i];
    }
#pragma unroll
    for (int off = 16; off; off >>= 1) sum += __shfl_xor_sync(0xffffffffu, sum, off);
    float inv = 1.f / sum;
#pragma unroll
    for (int i = 0; i < 16; i++) p[lane + 32 * i] = v[i] * inv;
}

// ---------------- emissions (24 CRF logits) + 2-class log-softmax head --------
__global__ __launch_bounds__(256) void emissions_kernel(
    const float* __restrict__ dec,
    const float* __restrict__ crf_w, const float* __restrict__ crf_b,
    const float* __restrict__ ent_w, const float* __restrict__ ent_b,
    float* __restrict__ em, float* __restrict__ seg_out)
{
    int row = blockIdx.x * 8 + (threadIdx.x >> 5);
    int lane = threadIdx.x & 31;
    const float* a = dec + (long long)row * 512;

    float acc[26];
#pragma unroll
    for (int o = 0; o < 26; o++) acc[o] = 0.f;

    for (int kk = lane; kk < 512; kk += 32) {
        float av = a[kk];
#pragma unroll
        for (int o = 0; o < 24; o++) acc[o] += av * crf_w[o * 512 + kk];
        acc[24] += av * ent_w[kk];
        acc[25] += av * ent_w[512 + kk];
    }
#pragma unroll
    for (int o = 0; o < 26; o++) {
#pragma unroll
        for (int off = 16; off; off >>= 1) acc[o] += __shfl_down_sync(0xffffffffu, acc[o], off);
    }
    if (lane == 0) {
#pragma unroll
        for (int o = 0; o < 24; o++) em[(long long)row * 24 + o] = acc[o] + crf_b[o];
        float z0 = acc[24] + ent_b[0];
        float z1 = acc[25] + ent_b[1];
        float m = fmaxf(z0, z1);
        float l = m + logf(expf(z0 - m) + expf(z1 - m));
        seg_out[(long long)row * 2 + 0] = z0 - l;
        seg_out[(long long)row * 2 + 1] = z1 - l;
    }
}

// ---------------- CRF: numerator + forward (logsumexp) + Viterbi --------------
__global__ __launch_bounds__(64) void crf_kernel(
    const float* __restrict__ em, const int* __restrict__ labels,
    const float* __restrict__ start_t, const float* __restrict__ end_t,
    const float* __restrict__ trans,
    float* __restrict__ out_crf, float* __restrict__ llh_part)
{
    __shared__ float tr[24 * 24];
    __shared__ float lse[24], vit[24];
    __shared__ unsigned char hist[511 * 24];
    __shared__ float red[64];
    __shared__ float s_num;

    int b = blockIdx.x, tid = threadIdx.x;
    const float* e0 = em + (long long)b * 512 * 24;
    const int* lab = labels + b * 512;

    for (int i = tid; i < 576; i += 64) tr[i] = trans[i];
    __syncthreads();

    float local = 0.f;
    for (int t = 1 + tid; t < 512; t += 64) {
        int lp = lab[t - 1], lc = lab[t];
        local += tr[lp * 24 + lc] + e0[t * 24 + lc];
    }
    red[tid] = local;
    if (tid < 24) { float v = start_t[tid] + e0[tid]; lse[tid] = v; vit[tid] = v; }
    __syncthreads();
    if (tid == 0) {
        float s = 0.f;
        for (int i = 0; i < 64; i++) s += red[i];
        int l0 = lab[0], lN = lab[511];
        s_num = s + start_t[l0] + e0[l0] + end_t[lN];
    }
    __syncthreads();

    for (int t = 1; t < 512; t++) {
        const float* e = e0 + t * 24;
        float nl = 0.f, nv = 0.f;
        int bi = 0;
        if (tid < 24) {
            int j = tid;
            float m = -1e30f;
#pragma unroll
            for (int i = 0; i < 24; i++) m = fmaxf(m, lse[i] + tr[i * 24 + j]);
            float s = 0.f;
#pragma unroll
            for (int i = 0; i < 24; i++) s += __expf(lse[i] + tr[i * 24 + j] - m);
            nl = m + __logf(s) + e[j];
        } else if (tid >= 32 && tid < 56) {
            int j = tid - 32;
            float bm = -1e30f;
#pragma unroll
            for (int i = 0; i < 24; i++) {
                float v = vit[i] + tr[i * 24 + j];
                if (v > bm) { bm = v; bi = i; }   // strict > : first-max like jnp.argmax
            }
            nv = bm + e[j];
        }
        __syncthreads();
        if (tid < 24) lse[tid] = nl;
        else if (tid >= 32 && tid < 56) {
            vit[tid - 32] = nv;
            hist[(t - 1) * 24 + (tid - 32)] = (unsigned char)bi;
        }
        __syncthreads();
    }

    if (tid == 0) {
        float m = -1e30f;
        for (int j = 0; j < 24; j++) m = fmaxf(m, lse[j] + end_t[j]);
        float s = 0.f;
        for (int j = 0; j < 24; j++) s += __expf(lse[j] + end_t[j] - m);
        float den = m + __logf(s);
        llh_part[b] = s_num - den;
    }
    if (tid == 32) {
        float bm = -1e30f;
        int last = 0;
        for (int j = 0; j < 24; j++) {
            float v = vit[j] + end_t[j];
            if (v > bm) { bm = v; last = j; }
        }
        out_crf[b * 512 + 511] = (float)last;
        int tag = last;
        for (int t = 510; t >= 0; t--) {
            tag = hist[t * 24 + tag];
            out_crf[b * 512 + t] = (float)tag;
        }
    }
}

__global__ void finalize_kernel(const float* __restrict__ llh_part, float* __restrict__ out_scalar)
{
    if (threadIdx.x == 0) {
        float s = 0.f;
        for (int i = 0; i < 32; i++) s += llh_part[i];
        *out_scalar = -s / 16384.0f;
    }
}

// --------------------------------- launch -------------------------------------
extern "C" void kernel_launch(void* const* d_in, const int* in_sizes, int n_in,
                              void* d_out, int out_size)
{
    const float* enc     = (const float*)d_in[0];   // (32,512,512)
    const int*   labels  = (const int*)d_in[1];     // (32,512)
    // d_in[2] = mask (all ones) — unused
    const float* Win     = (const float*)d_in[3];   // (1536,512)
    const float* bin_    = (const float*)d_in[4];   // (1536,)
    const float* Wout    = (const float*)d_in[5];   // (512,512)
    const float* bout    = (const float*)d_in[6];   // (512,)
    const float* crf_w   = (const float*)d_in[7];   // (24,512)
    const float* crf_b   = (const float*)d_in[8];   // (24,)
    const float* start_t = (const float*)d_in[9];   // (24,)
    const float* end_t   = (const float*)d_in[10];  // (24,)
    const float* trans   = (const float*)d_in[11];  // (24,24)
    const float* ent_w   = (const float*)d_in[12];  // (2,512)
    const float* ent_b   = (const float*)d_in[13];  // (2,)

    float* out = (float*)d_out;  // [crf_out 16384 | seg_out 32768 | -llh 1]

    float *qkv, *vt, *scores, *attn, *dec, *em, *llh;
    cudaGetSymbolAddress((void**)&qkv, g_qkv);
    cudaGetSymbolAddress((void**)&vt, g_vt);
    cudaGetSymbolAddress((void**)&scores, g_scores);
    cudaGetSymbolAddress((void**)&attn, g_attn);
    cudaGetSymbolAddress((void**)&dec, g_dec);
    cudaGetSymbolAddress((void**)&em, g_em);
    cudaGetSymbolAddress((void**)&llh, g_llh);

    // 1) QKV = enc @ Win^T + bin : (16384 x 1536), K=512
    mma_gemm_kernel<<<dim3(12, 128, 1), 256>>>(
        enc, 512, 0, 0,
        Win, 512, 0, 0,
        qkv, 1536, 0, 0,
        bin_, 512, 1.0f, 1, 1);

    // 2) V transpose: per (b,h) -> vt[d][s]
    transpose_v<<<dim3(16, 8, 64), dim3(32, 8)>>>(qkv, vt);

    // 3) scores[b,h] = Q @ K^T / 16 : 64 batched (512 x 512), K=256
    mma_gemm_kernel<<<dim3(4, 4, 64), 256>>>(
        qkv,        1536, 512LL * 1536, 256,
        qkv + 512,  1536, 512LL * 1536, 256,
        scores,     512,  524288LL,     262144LL,
        nullptr, 256, 0.0625f, 1, 2);

    // 4) softmax over rows
    softmax_rows<<<4096, 256>>>(scores);

    // 5) attn_out[b,h] = P @ Vt^T : 64 batched (512 x 256), K=512
    mma_gemm_kernel<<<dim3(2, 4, 64), 256>>>(
        scores, 512, 524288LL, 262144LL,
        vt,     512, 262144LL, 131072LL,
        attn,   512, 262144LL, 256LL,
        nullptr, 512, 1.0f, 1, 2);

    // 6) dec = relu(attn @ Wout^T + bout) : (16384 x 512), K=512
    mma_gemm_kernel<<<dim3(4, 128, 1), 256>>>(
        attn, 512, 0, 0,
        Wout, 512, 0, 0,
        dec,  512, 0, 0,
        bout, 512, 1.0f, 3, 1);

    // 7) emissions (24) + seg log-softmax (2); seg written straight into d_out
    emissions_kernel<<<2048, 256>>>(dec, crf_w, crf_b, ent_w, ent_b, em, out + 16384);

    // 8) CRF scan: numerator + normalizer + Viterbi (+ backtrack into d_out)
    crf_kernel<<<32, 64>>>(em, labels, start_t, end_t, trans, out, llh);

    // 9) scalar -llh
    finalize_kernel<<<1, 32>>>(llh, out + 16384 + 32768);
}

// round 13
// speedup vs baseline: 1.8292x; 1.0930x over previous
#include <cuda_runtime.h>
#include <cuda_fp16.h>
#include <math.h>
#include <stdint.h>

// ---------------- scratch (static device arrays; no allocation) ----------------
__device__ float g_qkv[16384 * 1536];      // QKV projection output
__device__ float g_vt[64 * 256 * 512];     // V transposed per (b,h): [d][s]
__device__ float g_scores[64 * 512 * 512]; // attention scores / probs
__device__ float g_attn[16384 * 512];      // attention output (pre out-proj)
__device__ float g_dec[16384 * 512];       // decoder features after ReLU
__device__ float g_em[16384 * 24];         // CRF emissions
__device__ float g_llh[32];                // per-batch (num - den)

// ---------------- fp16 split helper (hi/lo, ~2^-22 combined precision) --------
__device__ __forceinline__ void pack2(float x0, float x1, uint32_t& h, uint32_t& l)
{
    __half h0 = __float2half_rn(x0);
    __half h1 = __float2half_rn(x1);
    __half l0 = __float2half_rn(x0 - __half2float(h0));
    __half l1 = __float2half_rn(x1 - __half2float(h1));
    h = (uint32_t)__half_as_ushort(h0) | ((uint32_t)__half_as_ushort(h1) << 16);
    l = (uint32_t)__half_as_ushort(l0) | ((uint32_t)__half_as_ushort(l1) << 16);
}

#define MMA_F16(d, a, b0, b1)                                               \
    asm("mma.sync.aligned.m16n8k16.row.col.f32.f16.f16.f32 "                \
        "{%0,%1,%2,%3}, {%4,%5,%6,%7}, {%8,%9}, {%0,%1,%2,%3};"             \
        : "+f"(d[0]), "+f"(d[1]), "+f"(d[2]), "+f"(d[3])                    \
        : "r"(a[0]), "r"(a[1]), "r"(a[2]), "r"(a[3]), "r"(b0), "r"(b1))

// ---------------- fp16x3 GEMM: C = act(alpha * A @ B^T + bias) -----------------
// A: MxK row-major (lda). B: NxK row-major (ldb) -- ALWAYS transB.
// Batched via z. Tile 128x256x16; 512 threads = 16 warps as 2(m) x 8(n);
// warp tile 64x32 (4x4 m16n8k16 frags). 2-stage smem ring, ONE barrier/chunk.
// SMEM planes: A word(cq,idx,khi) = cq*264 + idx*2 + khi   (idx<128)
//              B word(cq,idx,khi) = cq*520 + idx*2 + khi   (idx<256)
// (264 and 520 are both ==8 mod 32: stores hit 32 distinct banks; frag LDS.64
//  conflict-free per 16-lane phase -- measured clean in R7.)
#define GBM 128
#define GBN 256
#define GBK 16
#define A_PLANE 1056
#define B_PLANE 2080
#define STW (2 * A_PLANE + 2 * B_PLANE)   // 6272 words per stage
#define SMEM_BYTES (2 * STW * 4)          // 50176 bytes

__global__ __launch_bounds__(512, 1) void mma_gemm_kernel(
    const float* __restrict__ A, int lda, long long aOuter, long long aInner,
    const float* __restrict__ B, int ldb, long long bOuter, long long bInner,
    float* __restrict__ C, int ldc, long long cOuter, long long cInner,
    const float* __restrict__ bias,
    int K, float alpha, int flags, int zdiv)
{
    extern __shared__ uint32_t sm[];
    int z = blockIdx.z;
    A += (long long)(z / zdiv) * aOuter + (long long)(z % zdiv) * aInner;
    B += (long long)(z / zdiv) * bOuter + (long long)(z % zdiv) * bInner;
    C += (long long)(z / zdiv) * cOuter + (long long)(z % zdiv) * cInner;

    int tid = threadIdx.x;
    int lane = tid & 31;
    int wid = tid >> 5;
    int r = lane >> 2;         // 0..7
    int cq = lane & 3;         // 0..3
    int wm = (wid >> 3) * 64;  // warp m offset (2 warp-rows)
    int wn = (wid & 7) * 32;   // warp n offset (8 warp-cols)
    int bm = blockIdx.y * GBM, bn = blockIdx.x * GBN;

    int ar = tid >> 2, akq = tid & 3;   // A: row 0..127, k-quad
    int br = tid >> 1, bkh = tid & 1;   // B: row 0..255, k-half

    float acc[4][4][4];
#pragma unroll
    for (int i = 0; i < 4; i++)
#pragma unroll
        for (int j = 0; j < 4; j++)
#pragma unroll
            for (int q = 0; q < 4; q++) acc[i][j][q] = 0.f;

    float4 pa, pb0, pb1;

#define LOAD_CHUNK(c) do {                                                           \
    pa  = *(const float4*)&A[(long long)(bm + ar) * lda + (c) * GBK + akq * 4];      \
    pb0 = *(const float4*)&B[(long long)(bn + br) * ldb + (c) * GBK + bkh * 8];      \
    pb1 = *(const float4*)&B[(long long)(bn + br) * ldb + (c) * GBK + bkh * 8 + 4];  \
} while (0)

#define STORE_CHUNK(base) do {                                                       \
    uint32_t* sAh = (base);                                                          \
    uint32_t* sAl = (base) + A_PLANE;                                                \
    uint32_t* sBh = (base) + 2 * A_PLANE;                                            \
    uint32_t* sBl = (base) + 2 * A_PLANE + B_PLANE;                                  \
    uint32_t _h, _l;                                                                 \
    int _k2 = 2 * akq;                                                               \
    pack2(pa.x, pa.y, _h, _l);                                                       \
    int _o = (_k2 & 3) * 264 + ar * 2 + (_k2 >> 2);                                  \
    sAh[_o] = _h; sAl[_o] = _l;                                                      \
    _k2 = 2 * akq + 1;                                                               \
    pack2(pa.z, pa.w, _h, _l);                                                       \
    _o = (_k2 & 3) * 264 + ar * 2 + (_k2 >> 2);                                      \
    sAh[_o] = _h; sAl[_o] = _l;                                                      \
    float _bv[8] = {pb0.x, pb0.y, pb0.z, pb0.w, pb1.x, pb1.y, pb1.z, pb1.w};         \
    _Pragma("unroll")                                                                \
    for (int p = 0; p < 4; p++) {                                                    \
        int _kb = 4 * bkh + p;                                                       \
        pack2(_bv[2 * p], _bv[2 * p + 1], _h, _l);                                   \
        int _ob = (_kb & 3) * 520 + br * 2 + (_kb >> 2);                             \
        sBh[_ob] = _h; sBl[_ob] = _l;                                                \
    }                                                                                \
} while (0)

    int nk = K / GBK;
    LOAD_CHUNK(0);
    STORE_CHUNK(sm);

    for (int c = 0; c < nk; c++) {
        if (c + 1 < nk) LOAD_CHUNK(c + 1);   // prefetch overlaps MMA below
        __syncthreads();                     // buf[c&1] visible; MMA(c-1) all done

        uint32_t* base = sm + (c & 1) * STW;
        uint32_t* sAh = base;
        uint32_t* sAl = base + A_PLANE;
        uint32_t* sBh = base + 2 * A_PLANE;
        uint32_t* sBl = base + 2 * A_PLANE + B_PLANE;

        uint32_t afh[4][4], afl[4][4];
#pragma unroll
        for (int i = 0; i < 4; i++) {
            int mi = wm + 16 * i + r;
            uint2 h0 = *(const uint2*)&sAh[cq * 264 + mi * 2];
            uint2 h1 = *(const uint2*)&sAh[cq * 264 + (mi + 8) * 2];
            uint2 l0 = *(const uint2*)&sAl[cq * 264 + mi * 2];
            uint2 l1 = *(const uint2*)&sAl[cq * 264 + (mi + 8) * 2];
            afh[i][0] = h0.x; afh[i][1] = h1.x; afh[i][2] = h0.y; afh[i][3] = h1.y;
            afl[i][0] = l0.x; afl[i][1] = l1.x; afl[i][2] = l0.y; afl[i][3] = l1.y;
        }
#pragma unroll
        for (int j = 0; j < 4; j++) {
            int ni = wn + 8 * j + r;
            uint2 bh = *(const uint2*)&sBh[cq * 520 + ni * 2];
            uint2 bl = *(const uint2*)&sBl[cq * 520 + ni * 2];
#pragma unroll
            for (int i = 0; i < 4; i++) {
                MMA_F16(acc[i][j], afh[i], bh.x, bh.y);  // hi * hi
                MMA_F16(acc[i][j], afl[i], bh.x, bh.y);  // lo * hi
                MMA_F16(acc[i][j], afh[i], bl.x, bl.y);  // hi * lo
            }
        }
        if (c + 1 < nk) STORE_CHUNK(sm + ((c + 1) & 1) * STW);
    }

    // ---- epilogue ----
    bool relu = (flags & 2) != 0;
#pragma unroll
    for (int i = 0; i < 4; i++) {
        int row0 = bm + wm + 16 * i + r;
#pragma unroll
        for (int j = 0; j < 4; j++) {
            int col0 = bn + wn + 8 * j + 2 * cq;
            float bv0 = bias ? bias[col0] : 0.f;
            float bv1 = bias ? bias[col0 + 1] : 0.f;
            float v0 = alpha * acc[i][j][0] + bv0;
            float v1 = alpha * acc[i][j][1] + bv1;
            float v2 = alpha * acc[i][j][2] + bv0;
            float v3 = alpha * acc[i][j][3] + bv1;
            if (relu) {
                v0 = fmaxf(v0, 0.f); v1 = fmaxf(v1, 0.f);
                v2 = fmaxf(v2, 0.f); v3 = fmaxf(v3, 0.f);
            }
            *(float2*)&C[(long long)row0 * ldc + col0] = make_float2(v0, v1);
            *(float2*)&C[(long long)(row0 + 8) * ldc + col0] = make_float2(v2, v3);
        }
    }
#undef LOAD_CHUNK
#undef STORE_CHUNK
}

// ---------------- V transpose: qkv V-part (s,d) -> vt[(b,h)][d][s] -------------
__global__ __launch_bounds__(256) void transpose_v(
    const float* __restrict__ qkv, float* __restrict__ vt)
{
    __shared__ float t[32][33];
    int z = blockIdx.z;
    int b = z >> 1, h = z & 1;
    int s0 = blockIdx.x * 32, d0 = blockIdx.y * 32;
    const float* src = qkv + (long long)b * 512 * 1536 + 1024 + h * 256;
#pragma unroll
    for (int yy = 0; yy < 4; yy++) {
        int sl = threadIdx.y + 8 * yy;
        t[sl][threadIdx.x] = src[(long long)(s0 + sl) * 1536 + d0 + threadIdx.x];
    }
    __syncthreads();
    float* dst = vt + (long long)z * 131072 + (long long)d0 * 512 + s0;
#pragma unroll
    for (int yy = 0; yy < 4; yy++) {
        int dl = threadIdx.y + 8 * yy;
        dst[(long long)dl * 512 + threadIdx.x] = t[threadIdx.x][dl];
    }
}

// ---------------- row softmax over 512 columns (warp per row) ----------------
__global__ __launch_bounds__(256) void softmax_rows(float* __restrict__ s)
{
    int row = blockIdx.x * 8 + (threadIdx.x >> 5);
    int lane = threadIdx.x & 31;
    float* p = s + (long long)row * 512;

    float v[16];
    float m = -1e30f;
#pragma unroll
    for (int i = 0; i < 16; i++) {
        v[i] = p[lane + 32 * i];
        m = fmaxf(m, v[i]);
    }
#pragma unroll
    for (int off = 16; off; off >>= 1) m = fmaxf(m, __shfl_xor_sync(0xffffffffu, m, off));
    float sum = 0.f;
#pragma unroll
    for (int i = 0; i < 16; i++) {
        v[i] = expf(v[i] - m);   // accurate exp: Viterbi-upstream
        sum += v[i];
    }
#pragma unroll
    for (int off = 16; off; off >>= 1) sum += __shfl_xor_sync(0xffffffffu, sum, off);
    float inv = 1.f / sum;
#pragma unroll
    for (int i = 0; i < 16; i++) p[lane + 32 * i] = v[i] * inv;
}

// ---------------- emissions (24 CRF logits) + 2-class log-softmax head --------
__global__ __launch_bounds__(256) void emissions_kernel(
    const float* __restrict__ dec,
    const float* __restrict__ crf_w, const float* __restrict__ crf_b,
    const float* __restrict__ ent_w, const float* __restrict__ ent_b,
    float* __restrict__ em, float* __restrict__ seg_out)
{
    int row = blockIdx.x * 8 + (threadIdx.x >> 5);
    int lane = threadIdx.x & 31;
    const float* a = dec + (long long)row * 512;

    float acc[26];
#pragma unroll
    for (int o = 0; o < 26; o++) acc[o] = 0.f;

    for (int kk = lane; kk < 512; kk += 32) {
        float av = a[kk];
#pragma unroll
        for (int o = 0; o < 24; o++) acc[o] += av * crf_w[o * 512 + kk];
        acc[24] += av * ent_w[kk];
        acc[25] += av * ent_w[512 + kk];
    }
#pragma unroll
    for (int o = 0; o < 26; o++) {
#pragma unroll
        for (int off = 16; off; off >>= 1) acc[o] += __shfl_down_sync(0xffffffffu, acc[o], off);
    }
    if (lane == 0) {
#pragma unroll
        for (int o = 0; o < 24; o++) em[(long long)row * 24 + o] = acc[o] + crf_b[o];
        float z0 = acc[24] + ent_b[0];
        float z1 = acc[25] + ent_b[1];
        float m = fmaxf(z0, z1);
        float l = m + logf(expf(z0 - m) + expf(z1 - m));
        seg_out[(long long)row * 2 + 0] = z0 - l;
        seg_out[(long long)row * 2 + 1] = z1 - l;
    }
}

// ---------------- CRF: numerator + forward (logsumexp) + Viterbi --------------
__global__ __launch_bounds__(64) void crf_kernel(
    const float* __restrict__ em, const int* __restrict__ labels,
    const float* __restrict__ start_t, const float* __restrict__ end_t,
    const float* __restrict__ trans,
    float* __restrict__ out_crf, float* __restrict__ llh_part)
{
    __shared__ float tr[24 * 24];
    __shared__ float lse[24], vit[24];
    __shared__ unsigned char hist[511 * 24];
    __shared__ float red[64];
    __shared__ float s_num;

    int b = blockIdx.x, tid = threadIdx.x;
    const float* e0 = em + (long long)b * 512 * 24;
    const int* lab = labels + b * 512;

    for (int i = tid; i < 576; i += 64) tr[i] = trans[i];
    __syncthreads();

    float local = 0.f;
    for (int t = 1 + tid; t < 512; t += 64) {
        int lp = lab[t - 1], lc = lab[t];
        local += tr[lp * 24 + lc] + e0[t * 24 + lc];
    }
    red[tid] = local;
    if (tid < 24) { float v = start_t[tid] + e0[tid]; lse[tid] = v; vit[tid] = v; }
    __syncthreads();
    if (tid == 0) {
        float s = 0.f;
        for (int i = 0; i < 64; i++) s += red[i];
        int l0 = lab[0], lN = lab[511];
        s_num = s + start_t[l0] + e0[l0] + end_t[lN];
    }
    __syncthreads();

    for (int t = 1; t < 512; t++) {
        const float* e = e0 + t * 24;
        float nl = 0.f, nv = 0.f;
        int bi = 0;
        if (tid < 24) {
            int j = tid;
            float m = -1e30f;
#pragma unroll
            for (int i = 0; i < 24; i++) m = fmaxf(m, lse[i] + tr[i * 24 + j]);
            float s = 0.f;
#pragma unroll
            for (int i = 0; i < 24; i++) s += __expf(lse[i] + tr[i * 24 + j] - m);
            nl = m + __logf(s) + e[j];
        } else if (tid >= 32 && tid < 56) {
            int j = tid - 32;
            float bm = -1e30f;
#pragma unroll
            for (int i = 0; i < 24; i++) {
                float v = vit[i] + tr[i * 24 + j];
                if (v > bm) { bm = v; bi = i; }   // strict > : first-max like jnp.argmax
            }
            nv = bm + e[j];
        }
        __syncthreads();
        if (tid < 24) lse[tid] = nl;
        else if (tid >= 32 && tid < 56) {
            vit[tid - 32] = nv;
            hist[(t - 1) * 24 + (tid - 32)] = (unsigned char)bi;
        }
        __syncthreads();
    }

    if (tid == 0) {
        float m = -1e30f;
        for (int j = 0; j < 24; j++) m = fmaxf(m, lse[j] + end_t[j]);
        float s = 0.f;
        for (int j = 0; j < 24; j++) s += __expf(lse[j] + end_t[j] - m);
        float den = m + __logf(s);
        llh_part[b] = s_num - den;
    }
    if (tid == 32) {
        float bm = -1e30f;
        int last = 0;
        for (int j = 0; j < 24; j++) {
            float v = vit[j] + end_t[j];
            if (v > bm) { bm = v; last = j; }
        }
        out_crf[b * 512 + 511] = (float)last;
        int tag = last;
        for (int t = 510; t >= 0; t--) {
            tag = hist[t * 24 + tag];
            out_crf[b * 512 + t] = (float)tag;
        }
    }
}

__global__ void finalize_kernel(const float* __restrict__ llh_part, float* __restrict__ out_scalar)
{
    if (threadIdx.x == 0) {
        float s = 0.f;
        for (int i = 0; i < 32; i++) s += llh_part[i];
        *out_scalar = -s / 16384.0f;
    }
}

// --------------------------------- launch -------------------------------------
extern "C" void kernel_launch(void* const* d_in, const int* in_sizes, int n_in,
                              void* d_out, int out_size)
{
    const float* enc     = (const float*)d_in[0];   // (32,512,512)
    const int*   labels  = (const int*)d_in[1];     // (32,512)
    // d_in[2] = mask (all ones) — unused
    const float* Win     = (const float*)d_in[3];   // (1536,512)
    const float* bin_    = (const float*)d_in[4];   // (1536,)
    const float* Wout    = (const float*)d_in[5];   // (512,512)
    const float* bout    = (const float*)d_in[6];   // (512,)
    const float* crf_w   = (const float*)d_in[7];   // (24,512)
    const float* crf_b   = (const float*)d_in[8];   // (24,)
    const float* start_t = (const float*)d_in[9];   // (24,)
    const float* end_t   = (const float*)d_in[10];  // (24,)
    const float* trans   = (const float*)d_in[11];  // (24,24)
    const float* ent_w   = (const float*)d_in[12];  // (2,512)
    const float* ent_b   = (const float*)d_in[13];  // (2,)

    float* out = (float*)d_out;  // [crf_out 16384 | seg_out 32768 | -llh 1]

    float *qkv, *vt, *scores, *attn, *dec, *em, *llh;
    cudaGetSymbolAddress((void**)&qkv, g_qkv);
    cudaGetSymbolAddress((void**)&vt, g_vt);
    cudaGetSymbolAddress((void**)&scores, g_scores);
    cudaGetSymbolAddress((void**)&attn, g_attn);
    cudaGetSymbolAddress((void**)&dec, g_dec);
    cudaGetSymbolAddress((void**)&em, g_em);
    cudaGetSymbolAddress((void**)&llh, g_llh);

    cudaFuncSetAttribute(mma_gemm_kernel,
                         cudaFuncAttributeMaxDynamicSharedMemorySize, SMEM_BYTES);

    // 1) QKV = enc @ Win^T + bin : (16384 x 1536), K=512
    mma_gemm_kernel<<<dim3(6, 128, 1), 512, SMEM_BYTES>>>(
        enc, 512, 0, 0,
        Win, 512, 0, 0,
        qkv, 1536, 0, 0,
        bin_, 512, 1.0f, 1, 1);

    // 2) V transpose: per (b,h) -> vt[d][s]
    transpose_v<<<dim3(16, 8, 64), dim3(32, 8)>>>(qkv, vt);

    // 3) scores[b,h] = Q @ K^T / 16 : 64 batched (512 x 512), K=256
    mma_gemm_kernel<<<dim3(2, 4, 64), 512, SMEM_BYTES>>>(
        qkv,        1536, 512LL * 1536, 256,
        qkv + 512,  1536, 512LL * 1536, 256,
        scores,     512,  524288LL,     262144LL,
        nullptr, 256, 0.0625f, 1, 2);

    // 4) softmax over rows
    softmax_rows<<<4096, 256>>>(scores);

    // 5) attn_out[b,h] = P @ Vt^T : 64 batched (512 x 256), K=512
    mma_gemm_kernel<<<dim3(1, 4, 64), 512, SMEM_BYTES>>>(
        scores, 512, 524288LL, 262144LL,
        vt,     512, 262144LL, 131072LL,
        attn,   512, 262144LL, 256LL,
        nullptr, 512, 1.0f, 1, 2);

    // 6) dec = relu(attn @ Wout^T + bout) : (16384 x 512), K=512
    mma_gemm_kernel<<<dim3(2, 128, 1), 512, SMEM_BYTES>>>(
        attn, 512, 0, 0,
        Wout, 512, 0, 0,
        dec,  512, 0, 0,
        bout, 512, 1.0f, 3, 1);

    // 7) emissions (24) + seg log-softmax (2); seg written straight into d_out
    emissions_kernel<<<2048, 256>>>(dec, crf_w, crf_b, ent_w, ent_b, em, out + 16384);

    // 8) CRF scan: numerator + normalizer + Viterbi (+ backtrack into d_out)
    crf_kernel<<<32, 64>>>(em, labels, start_t, end_t, trans, out, llh);

    // 9) scalar -llh
    finalize_kernel<<<1, 32>>>(llh, out + 16384 + 32768);
}